// round 2
// baseline (speedup 1.0000x reference)
#include <cuda_runtime.h>

// Problem constants
#define BB   8
#define NCTX 3
#define CC   64
#define FF   128
#define HFINE 128
#define WFINE 128
#define HCO  64
#define WCO  64

typedef unsigned long long u64t;

// ------------------------- scratch (device globals) -------------------------
__device__ float g_W2p[64 * 128 * 2];          // packed [opair][f][2]  (qt rows 0-63, k rows 64-127)
__device__ float g_bias2[128];                  // qt bias (Wc^T bf) || bk
__device__ float g_Vwp[128 * 32 * 9 * 2];       // packed conv weights [f][cpair][tap][2]
__device__ float g_qt[BB * CC * HCO * WCO];     // [b][c][hc][wc]
__device__ float g_vals[BB * CC * HCO * WCO];   // [b][c][hc][wc]
__device__ float g_ml[BB * HCO * WCO];          // main-branch logit

// ------------------------- f32x2 helpers -------------------------
__device__ __forceinline__ u64t splat2(float x) {
    u64t r; asm("mov.b64 %0, {%1, %1};" : "=l"(r) : "f"(x)); return r;
}
__device__ __forceinline__ u64t pack2(float x, float y) {
    u64t r; asm("mov.b64 %0, {%1, %2};" : "=l"(r) : "f"(x), "f"(y)); return r;
}
__device__ __forceinline__ void fma2(u64t& d, u64t a, u64t b) {
    asm("fma.rn.f32x2 %0, %1, %2, %0;" : "+l"(d) : "l"(a), "l"(b));
}
__device__ __forceinline__ float2 unpack2(u64t v) {
    float2 r; asm("mov.b64 {%0, %1}, %2;" : "=f"(r.x), "=f"(r.y) : "l"(v)); return r;
}

// ------------------------- prep kernels -------------------------
// W2[o][f]: o<64 -> (Wc^T Wf)[o][f] ; o>=64 -> Wk[o-64][f].  Packed into out-channel pairs.
__global__ void prep1(const float* __restrict__ Wc, const float* __restrict__ bf,
                      const float* __restrict__ Wf, const float* __restrict__ Wk,
                      const float* __restrict__ bk) {
    int o = blockIdx.x;      // 0..127
    int f = threadIdx.x;     // 0..127
    float v;
    if (o < 64) {
        v = 0.f;
        for (int d = 0; d < 64; d++) v += Wc[d * 64 + o] * Wf[d * 128 + f];
    } else {
        v = Wk[(o - 64) * 128 + f];
    }
    g_W2p[(o >> 1) * 256 + f * 2 + (o & 1)] = v;
    if (f == 0) {
        float bbv;
        if (o < 64) { bbv = 0.f; for (int d = 0; d < 64; d++) bbv += Wc[d * 64 + o] * bf[d]; }
        else bbv = bk[o - 64];
        g_bias2[o] = bbv;
    }
}

// Pack Vw [C][F][3][3] -> g_Vwp [f][cpair][tap][2]
__global__ void prep2(const float* __restrict__ Vw) {
    int i = blockIdx.x * 256 + threadIdx.x;
    if (i >= 128 * 32 * 9 * 2) return;
    int p   = i & 1;
    int q   = i >> 1;
    int tap = q % 9;
    int cp  = (q / 9) % 32;
    int f   = q / (9 * 32);
    g_Vwp[i] = Vw[((2 * cp + p) * 128 + f) * 9 + tap];
}

// ------------------------- coarse kernel -------------------------
// grid (64 hc, 8 b), 256 threads, dyn smem 204288 B
// smem: s_m[3][128][66] | s_W2[64][129]*float2 (aliased as qk after phase1) | s_Vw chunk [16][32][9]*float2
__global__ void __launch_bounds__(256, 1)
kcoarse(const float* __restrict__ ms, const float* __restrict__ Vb) {
    extern __shared__ float sm[];
    float* s_m  = sm;                      // 25344 floats
    float* s_W2 = sm + 25344;              // 16512 floats (64*129*2)
    float* s_Vw = sm + 25344 + 16512;      // 9216 floats

    const int hc  = blockIdx.x;
    const int b   = blockIdx.y;
    const int tid = threadIdx.x;
    const float* mb = ms + (size_t)b * 128 * 64 * 64;

    // load mainstream rows hc-1..hc+1 with zero halo
    for (int i = tid; i < 3 * 128 * 64; i += 256) {
        int w = i & 63;
        int f = (i >> 6) & 127;
        int r = i >> 13;
        int h = hc - 1 + r;
        float v = (h >= 0 && h < 64) ? mb[f * 4096 + h * 64 + w] : 0.f;
        s_m[(r * 128 + f) * 66 + 1 + w] = v;
    }
    for (int i = tid; i < 3 * 128; i += 256) { s_m[i * 66] = 0.f; s_m[i * 66 + 65] = 0.f; }
    // load W2 (row-padded to 129 float2 to dodge bank conflicts)
    for (int i = tid; i < 64 * 128; i += 256) {
        int op = i >> 7, f = i & 127;
        *(float2*)&s_W2[(op * 129 + f) * 2] = *(const float2*)&g_W2p[(op * 128 + f) * 2];
    }
    __syncthreads();

    // ---- phase 1: qt & k (1x1) ----
    const int pxg = tid & 15;      // 16 groups of 4 wc
    const int og  = tid >> 4;      // 16 groups of 4 out-pairs
    const int wc0 = pxg * 4;
    const int op0 = og * 4;

    u64t acc[4][4];
    #pragma unroll
    for (int p = 0; p < 4; p++) {
        u64t bi = pack2(g_bias2[(op0 + p) * 2], g_bias2[(op0 + p) * 2 + 1]);
        #pragma unroll
        for (int j = 0; j < 4; j++) acc[p][j] = bi;
    }
    const float* mrow = s_m + 128 * 66;    // center row (r=1)
    #pragma unroll 4
    for (int f = 0; f < 128; f++) {
        u64t ms4[4];
        #pragma unroll
        for (int j = 0; j < 4; j++) ms4[j] = splat2(mrow[f * 66 + 1 + wc0 + j]);
        u64t wp[4];
        #pragma unroll
        for (int p = 0; p < 4; p++) wp[p] = *(const u64t*)&s_W2[((op0 + p) * 129 + f) * 2];
        #pragma unroll
        for (int p = 0; p < 4; p++)
            #pragma unroll
            for (int j = 0; j < 4; j++) fma2(acc[p][j], ms4[j], wp[p]);
    }
    __syncthreads();

    // write qk into smem (alias W2 region) + qt to global
    float* s_qk = s_W2;   // [128][64]
    float* qtb  = g_qt + (size_t)b * 64 * 4096 + hc * 64;
    #pragma unroll
    for (int p = 0; p < 4; p++) {
        int o0 = (op0 + p) * 2;
        #pragma unroll
        for (int j = 0; j < 4; j++) {
            float2 v = unpack2(acc[p][j]);
            s_qk[o0 * 64 + wc0 + j]       = v.x;
            s_qk[(o0 + 1) * 64 + wc0 + j] = v.y;
            if (o0 < 64) {
                qtb[o0 * 4096 + wc0 + j]       = v.x;
                qtb[(o0 + 1) * 4096 + wc0 + j] = v.y;
            }
        }
    }
    __syncthreads();

    if (tid < 64) {
        float s = 0.f;
        #pragma unroll
        for (int c = 0; c < 64; c++) s += s_qk[c * 64 + tid] * s_qk[(64 + c) * 64 + tid];
        g_ml[((size_t)b * 64 + hc) * 64 + tid] = s;
    }

    // ---- phase 2: conv3x3 (values) ----
    const int cg = tid >> 4;   // 16 groups of 2 ch-pairs (4 channels)
    u64t vac[2][4];
    #pragma unroll
    for (int p = 0; p < 2; p++) {
        u64t bi = pack2(Vb[(cg * 2 + p) * 2], Vb[(cg * 2 + p) * 2 + 1]);
        #pragma unroll
        for (int j = 0; j < 4; j++) vac[p][j] = bi;
    }
    for (int fc = 0; fc < 8; fc++) {
        __syncthreads();
        for (int i = tid; i < 16 * 32 * 9; i += 256)
            *(float2*)&s_Vw[i * 2] = *(const float2*)&g_Vwp[(fc * 16 * 32 * 9 + i) * 2];
        __syncthreads();
        for (int fl = 0; fl < 16; fl++) {
            int f = fc * 16 + fl;
            u64t mm[3][6];
            #pragma unroll
            for (int r = 0; r < 3; r++)
                #pragma unroll
                for (int k = 0; k < 6; k++) mm[r][k] = splat2(s_m[(r * 128 + f) * 66 + wc0 + k]);
            u64t wv[2][9];
            #pragma unroll
            for (int t9 = 0; t9 < 9; t9++)
                #pragma unroll
                for (int p = 0; p < 2; p++)
                    wv[p][t9] = *(const u64t*)&s_Vw[((fl * 32 + cg * 2 + p) * 9 + t9) * 2];
            #pragma unroll
            for (int ky = 0; ky < 3; ky++)
                #pragma unroll
                for (int kx = 0; kx < 3; kx++)
                    #pragma unroll
                    for (int p = 0; p < 2; p++)
                        #pragma unroll
                        for (int j = 0; j < 4; j++)
                            fma2(vac[p][j], mm[ky][j + kx], wv[p][ky * 3 + kx]);
        }
    }
    float* vb2 = g_vals + (size_t)b * 64 * 4096 + hc * 64;
    #pragma unroll
    for (int p = 0; p < 2; p++) {
        int c0 = (cg * 2 + p) * 2;
        #pragma unroll
        for (int j = 0; j < 4; j++) {
            float2 v = unpack2(vac[p][j]);
            vb2[c0 * 4096 + wc0 + j]       = v.x;
            vb2[(c0 + 1) * 4096 + wc0 + j] = v.y;
        }
    }
}

// ------------------------- fine kernel -------------------------
// grid (64 hc, 8 b), 256 threads, dyn smem 229632 B
__global__ void __launch_bounds__(256, 1)
kfine(const float* __restrict__ ctx, float* __restrict__ out) {
    extern __shared__ float sf[];
    float* s_ctx = sf;              // [3][64][2][128] = 49152
    float* s_qt  = sf + 49152;      // [64][64]
    float* s_v   = sf + 53248;      // [64][64]
    float* s_ml  = sf + 57344;      // [64]

    const int hc  = blockIdx.x;
    const int b   = blockIdx.y;
    const int tid = threadIdx.x;

    const float* cb = ctx + (size_t)b * 3 * 64 * 16384 + hc * 256;  // rows 2hc,2hc+1
    for (int i = tid; i < 3 * 64 * 256; i += 256) {
        int nc = i >> 8;
        int r  = i & 255;
        s_ctx[i] = cb[(size_t)nc * 16384 + r];
    }
    const float* qtb = g_qt   + (size_t)b * 64 * 4096 + hc * 64;
    const float* vlb = g_vals + (size_t)b * 64 * 4096 + hc * 64;
    for (int i = tid; i < 64 * 64; i += 256) {
        int c = i >> 6, wc = i & 63;
        s_qt[i] = qtb[c * 4096 + wc];
        s_v[i]  = vlb[c * 4096 + wc];
    }
    if (tid < 64) s_ml[tid] = g_ml[((size_t)b * 64 + hc) * 64 + tid];
    __syncthreads();

    const int dy = tid >> 7;
    const int w  = tid & 127;
    const int wc = w >> 1;
    const float* cthis = s_ctx + dy * 128 + w;

    float l0 = 0.f, l1 = 0.f, l2 = 0.f;
    #pragma unroll 8
    for (int c = 0; c < 64; c++) {
        float q = s_qt[c * 64 + wc];
        l0 += cthis[(0 * 64 + c) * 256] * q;
        l1 += cthis[(1 * 64 + c) * 256] * q;
        l2 += cthis[(2 * 64 + c) * 256] * q;
    }
    float l3 = s_ml[wc];
    float mx = fmaxf(fmaxf(l0, l1), fmaxf(l2, l3));
    float e0 = expf(l0 - mx), e1 = expf(l1 - mx), e2 = expf(l2 - mx), e3 = expf(l3 - mx);
    float inv = 1.f / (e0 + e1 + e2 + e3);
    float a0 = e0 * inv, a1 = e1 * inv, a2 = e2 * inv, a3 = e3 * inv;

    float* ob = out + (size_t)b * 64 * 16384 + hc * 256 + dy * 128 + w;
    #pragma unroll 4
    for (int c = 0; c < 64; c++) {
        float r = cthis[(0 * 64 + c) * 256] * a0
                + cthis[(1 * 64 + c) * 256] * a1
                + cthis[(2 * 64 + c) * 256] * a2
                + s_v[c * 64 + wc] * a3;
        ob[(size_t)c * 16384] = r;
    }
}

// ------------------------- launch -------------------------
extern "C" void kernel_launch(void* const* d_in, const int* in_sizes, int n_in,
                              void* d_out, int out_size) {
    const float* contexts   = (const float*)d_in[0];
    const float* mainstream = (const float*)d_in[1];
    const float* Wc = (const float*)d_in[2];
    // d_in[3] = bc: adds a constant to every logit -> softmax-invariant -> unused
    const float* Wf = (const float*)d_in[4];
    const float* bf = (const float*)d_in[5];
    const float* Wk = (const float*)d_in[6];
    const float* bk = (const float*)d_in[7];
    const float* Vw = (const float*)d_in[8];
    const float* Vb = (const float*)d_in[9];

    cudaFuncSetAttribute(kcoarse, cudaFuncAttributeMaxDynamicSharedMemorySize, 204288);
    cudaFuncSetAttribute(kfine,   cudaFuncAttributeMaxDynamicSharedMemorySize, 229632);

    prep1<<<128, 128>>>(Wc, bf, Wf, Wk, bk);
    prep2<<<288, 256>>>(Vw);
    kcoarse<<<dim3(64, 8), 256, 204288>>>(mainstream, Vb);
    kfine<<<dim3(64, 8), 256, 229632>>>(contexts, (float*)d_out);
}

// round 3
// speedup vs baseline: 1.4728x; 1.4728x over previous
#include <cuda_runtime.h>

// Problem constants
#define BB   8
#define NCTX 3
#define CC   64
#define FF   128
#define HCO  64
#define WCO  64

typedef unsigned long long u64t;

// ------------------------- scratch (device globals) -------------------------
__device__ float g_W2p[64 * 128 * 2];           // packed [opair][f][2]  (qt rows 0-63, k rows 64-127)
__device__ float g_bias2[128];                  // qt bias (Wc^T bf) || bk
__device__ float g_Vwp[128 * 32 * 20];          // padded conv weights [f][cpair][20 floats: 9 u64 taps + pad]
__device__ float g_qt[BB * CC * HCO * WCO];     // [b][c][hc][wc]
__device__ float g_vals[BB * CC * HCO * WCO];   // [b][c][hc][wc]
__device__ float g_ml[BB * HCO * WCO];          // main-branch logit

// ------------------------- f32x2 helpers -------------------------
__device__ __forceinline__ u64t splat2(float x) {
    u64t r; asm("mov.b64 %0, {%1, %1};" : "=l"(r) : "f"(x)); return r;
}
__device__ __forceinline__ u64t pack2(float x, float y) {
    u64t r; asm("mov.b64 %0, {%1, %2};" : "=l"(r) : "f"(x), "f"(y)); return r;
}
__device__ __forceinline__ void fma2(u64t& d, u64t a, u64t b) {
    asm("fma.rn.f32x2 %0, %1, %2, %0;" : "+l"(d) : "l"(a), "l"(b));
}
__device__ __forceinline__ float2 unpack2(u64t v) {
    float2 r; asm("mov.b64 {%0, %1}, %2;" : "=f"(r.x), "=f"(r.y) : "l"(v)); return r;
}

// ------------------------- prep kernels -------------------------
__global__ void prep1(const float* __restrict__ Wc, const float* __restrict__ bf,
                      const float* __restrict__ Wf, const float* __restrict__ Wk,
                      const float* __restrict__ bk) {
    int o = blockIdx.x;      // 0..127
    int f = threadIdx.x;     // 0..127
    float v;
    if (o < 64) {
        v = 0.f;
        for (int d = 0; d < 64; d++) v += Wc[d * 64 + o] * Wf[d * 128 + f];
    } else {
        v = Wk[(o - 64) * 128 + f];
    }
    g_W2p[(o >> 1) * 256 + f * 2 + (o & 1)] = v;
    if (f == 0) {
        float bbv;
        if (o < 64) { bbv = 0.f; for (int d = 0; d < 64; d++) bbv += Wc[d * 64 + o] * bf[d]; }
        else bbv = bk[o - 64];
        g_bias2[o] = bbv;
    }
}

// Pack Vw [C][F][3][3] -> g_Vwp [f][cpair][slot<20], slot = tap*2 + p, slots 18,19 = pad
__global__ void prep2(const float* __restrict__ Vw) {
    int i = blockIdx.x * 256 + threadIdx.x;
    if (i >= 128 * 32 * 20) return;
    int slot = i % 20;
    int cp   = (i / 20) % 32;
    int f    = i / (20 * 32);
    float v = 0.f;
    if (slot < 18) {
        int p = slot & 1;
        int tap = slot >> 1;
        v = Vw[((2 * cp + p) * 128 + f) * 9 + tap];
    }
    g_Vwp[i] = v;
}

// ------------------------- coarse kernel -------------------------
// grid (64 hc, 8 b), 256 threads, dyn smem 208384 B
// smem: s_m[3][128][66] | s_W2[64][129]*float2 (aliased as qk after phase1) | s_Vw chunk [16][32][20]
__global__ void __launch_bounds__(256, 1)
kcoarse(const float* __restrict__ ms, const float* __restrict__ Vb) {
    extern __shared__ float sm[];
    float* s_m  = sm;                      // 25344 floats
    float* s_W2 = sm + 25344;              // 16512 floats (64*129*2)
    float* s_Vw = sm + 25344 + 16512;      // 10240 floats

    const int hc  = blockIdx.x;
    const int b   = blockIdx.y;
    const int tid = threadIdx.x;
    const float* mb = ms + (size_t)b * 128 * 64 * 64;

    // load mainstream rows hc-1..hc+1 with zero halo
    for (int i = tid; i < 3 * 128 * 64; i += 256) {
        int w = i & 63;
        int f = (i >> 6) & 127;
        int r = i >> 13;
        int h = hc - 1 + r;
        float v = (h >= 0 && h < 64) ? mb[f * 4096 + h * 64 + w] : 0.f;
        s_m[(r * 128 + f) * 66 + 1 + w] = v;
    }
    for (int i = tid; i < 3 * 128; i += 256) { s_m[i * 66] = 0.f; s_m[i * 66 + 65] = 0.f; }
    // load W2 (row-padded to 129 float2 to dodge bank conflicts)
    for (int i = tid; i < 64 * 128; i += 256) {
        int op = i >> 7, f = i & 127;
        *(float2*)&s_W2[(op * 129 + f) * 2] = *(const float2*)&g_W2p[(op * 128 + f) * 2];
    }
    __syncthreads();

    // ---- phase 1: qt & k (1x1) ----
    const int pxg = tid & 15;      // 16 groups of 4 wc
    const int og  = tid >> 4;      // 16 groups of 4 out-pairs
    const int wc0 = pxg * 4;
    const int op0 = og * 4;

    u64t acc[4][4];
    #pragma unroll
    for (int p = 0; p < 4; p++) {
        u64t bi = pack2(g_bias2[(op0 + p) * 2], g_bias2[(op0 + p) * 2 + 1]);
        #pragma unroll
        for (int j = 0; j < 4; j++) acc[p][j] = bi;
    }
    const float* mrow = s_m + 128 * 66;    // center row (r=1)
    #pragma unroll 4
    for (int f = 0; f < 128; f++) {
        u64t ms4[4];
        #pragma unroll
        for (int j = 0; j < 4; j++) ms4[j] = splat2(mrow[f * 66 + 1 + wc0 + j]);
        u64t wp[4];
        #pragma unroll
        for (int p = 0; p < 4; p++) wp[p] = *(const u64t*)&s_W2[((op0 + p) * 129 + f) * 2];
        #pragma unroll
        for (int p = 0; p < 4; p++)
            #pragma unroll
            for (int j = 0; j < 4; j++) fma2(acc[p][j], ms4[j], wp[p]);
    }
    __syncthreads();

    // write qk into smem (alias W2 region) + qt to global
    float* s_qk = s_W2;   // [128][64]
    float* qtb  = g_qt + (size_t)b * 64 * 4096 + hc * 64;
    #pragma unroll
    for (int p = 0; p < 4; p++) {
        int o0 = (op0 + p) * 2;
        #pragma unroll
        for (int j = 0; j < 4; j++) {
            float2 v = unpack2(acc[p][j]);
            s_qk[o0 * 64 + wc0 + j]       = v.x;
            s_qk[(o0 + 1) * 64 + wc0 + j] = v.y;
            if (o0 < 64) {
                qtb[o0 * 4096 + wc0 + j]       = v.x;
                qtb[(o0 + 1) * 4096 + wc0 + j] = v.y;
            }
        }
    }
    __syncthreads();

    if (tid < 64) {
        float s = 0.f;
        #pragma unroll
        for (int c = 0; c < 64; c++) s += s_qk[c * 64 + tid] * s_qk[(64 + c) * 64 + tid];
        g_ml[((size_t)b * 64 + hc) * 64 + tid] = s;
    }

    // ---- phase 2: conv3x3 (values) ----
    const int cg = tid >> 4;   // 16 groups of 2 ch-pairs (4 channels)
    u64t vac[2][4];
    #pragma unroll
    for (int p = 0; p < 2; p++) {
        u64t bi = pack2(Vb[(cg * 2 + p) * 2], Vb[(cg * 2 + p) * 2 + 1]);
        #pragma unroll
        for (int j = 0; j < 4; j++) vac[p][j] = bi;
    }
    for (int fc = 0; fc < 8; fc++) {
        __syncthreads();
        for (int i = tid; i < 2560; i += 256)
            *(float4*)&s_Vw[i * 4] = *(const float4*)&g_Vwp[fc * 10240 + i * 4];
        __syncthreads();
        #pragma unroll 2
        for (int fl = 0; fl < 16; fl++) {
            int f = fc * 16 + fl;
            // activations: 3 rows x 6 cols via float2 LDS, then splat
            u64t mm[3][6];
            #pragma unroll
            for (int r = 0; r < 3; r++) {
                const float* rp = &s_m[(r * 128 + f) * 66 + wc0];
                #pragma unroll
                for (int kk = 0; kk < 3; kk++) {
                    float2 v = *(const float2*)(rp + 2 * kk);
                    mm[r][2 * kk]     = splat2(v.x);
                    mm[r][2 * kk + 1] = splat2(v.y);
                }
            }
            // weights: padded 80B rows -> 4x LDS.128 + 1x LDS.64 per pair
            u64t wv[2][9];
            #pragma unroll
            for (int p = 0; p < 2; p++) {
                const float* wrow = &s_Vw[(fl * 32 + cg * 2 + p) * 20];
                float4 a0 = *(const float4*)(wrow + 0);
                float4 a1 = *(const float4*)(wrow + 4);
                float4 a2 = *(const float4*)(wrow + 8);
                float4 a3 = *(const float4*)(wrow + 12);
                float2 a4 = *(const float2*)(wrow + 16);
                wv[p][0] = pack2(a0.x, a0.y); wv[p][1] = pack2(a0.z, a0.w);
                wv[p][2] = pack2(a1.x, a1.y); wv[p][3] = pack2(a1.z, a1.w);
                wv[p][4] = pack2(a2.x, a2.y); wv[p][5] = pack2(a2.z, a2.w);
                wv[p][6] = pack2(a3.x, a3.y); wv[p][7] = pack2(a3.z, a3.w);
                wv[p][8] = pack2(a4.x, a4.y);
            }
            #pragma unroll
            for (int ky = 0; ky < 3; ky++)
                #pragma unroll
                for (int kx = 0; kx < 3; kx++)
                    #pragma unroll
                    for (int p = 0; p < 2; p++)
                        #pragma unroll
                        for (int j = 0; j < 4; j++)
                            fma2(vac[p][j], mm[ky][j + kx], wv[p][ky * 3 + kx]);
        }
    }
    float* vb2 = g_vals + (size_t)b * 64 * 4096 + hc * 64;
    #pragma unroll
    for (int p = 0; p < 2; p++) {
        int c0 = (cg * 2 + p) * 2;
        #pragma unroll
        for (int j = 0; j < 4; j++) {
            float2 v = unpack2(vac[p][j]);
            vb2[c0 * 4096 + wc0 + j]       = v.x;
            vb2[(c0 + 1) * 4096 + wc0 + j] = v.y;
        }
    }
}

// ------------------------- fine kernel (register-resident, no smem) -------------------------
// grid (2 whalf, 128 h, 8 b), 256 threads.
// warp = 8 px x 4 channel-groups; logit reduction via shfl_xor(8),(16).
__global__ void __launch_bounds__(256)
kfine2(const float* __restrict__ ctx, float* __restrict__ out) {
    const int b    = blockIdx.z;
    const int h    = blockIdx.y;
    const int warp = threadIdx.x >> 5;
    const int lane = threadIdx.x & 31;
    const int w    = blockIdx.x * 64 + warp * 8 + (lane & 7);
    const int cg   = lane >> 3;
    const int c0   = cg * 16;
    const int hc   = h >> 1;
    const int wc   = w >> 1;

    // context values for my 16 channels x 3 contexts -> registers (read ONCE)
    const float* cb = ctx + ((size_t)(b * 3) * 64 + c0) * 16384 + h * 128 + w;
    float r0[16], r1[16], r2[16];
    #pragma unroll
    for (int i = 0; i < 16; i++) {
        r0[i] = cb[(size_t)i * 16384];
        r1[i] = cb[(size_t)(64 + i) * 16384];
        r2[i] = cb[(size_t)(128 + i) * 16384];
    }

    // partial logits with transformed query
    const float* qb = g_qt + ((size_t)b * 64 + c0) * 4096 + hc * 64 + wc;
    float l0 = 0.f, l1 = 0.f, l2 = 0.f;
    #pragma unroll
    for (int i = 0; i < 16; i++) {
        float q = qb[(size_t)i * 4096];
        l0 += r0[i] * q; l1 += r1[i] * q; l2 += r2[i] * q;
    }
    // reduce across the 4 channel groups (lane bits 3,4)
    l0 += __shfl_xor_sync(0xFFFFFFFFu, l0, 8);
    l0 += __shfl_xor_sync(0xFFFFFFFFu, l0, 16);
    l1 += __shfl_xor_sync(0xFFFFFFFFu, l1, 8);
    l1 += __shfl_xor_sync(0xFFFFFFFFu, l1, 16);
    l2 += __shfl_xor_sync(0xFFFFFFFFu, l2, 8);
    l2 += __shfl_xor_sync(0xFFFFFFFFu, l2, 16);

    float l3 = g_ml[((size_t)b * 64 + hc) * 64 + wc];

    float mx = fmaxf(fmaxf(l0, l1), fmaxf(l2, l3));
    float e0 = __expf(l0 - mx), e1 = __expf(l1 - mx);
    float e2 = __expf(l2 - mx), e3 = __expf(l3 - mx);
    float inv = 1.f / (e0 + e1 + e2 + e3);
    float a0 = e0 * inv, a1 = e1 * inv, a2 = e2 * inv, a3 = e3 * inv;

    const float* vb = g_vals + ((size_t)b * 64 + c0) * 4096 + hc * 64 + wc;
    float* ob = out + ((size_t)b * 64 + c0) * 16384 + h * 128 + w;
    #pragma unroll
    for (int i = 0; i < 16; i++) {
        float o = r0[i] * a0 + r1[i] * a1 + r2[i] * a2 + vb[(size_t)i * 4096] * a3;
        ob[(size_t)i * 16384] = o;
    }
}

// ------------------------- launch -------------------------
extern "C" void kernel_launch(void* const* d_in, const int* in_sizes, int n_in,
                              void* d_out, int out_size) {
    const float* contexts   = (const float*)d_in[0];
    const float* mainstream = (const float*)d_in[1];
    const float* Wc = (const float*)d_in[2];
    // d_in[3] = bc: adds a constant to every logit -> softmax-invariant -> unused
    const float* Wf = (const float*)d_in[4];
    const float* bf = (const float*)d_in[5];
    const float* Wk = (const float*)d_in[6];
    const float* bk = (const float*)d_in[7];
    const float* Vw = (const float*)d_in[8];
    const float* Vb = (const float*)d_in[9];

    cudaFuncSetAttribute(kcoarse, cudaFuncAttributeMaxDynamicSharedMemorySize, 208384);

    prep1<<<128, 128>>>(Wc, bf, Wf, Wk, bk);
    prep2<<<320, 256>>>(Vw);
    kcoarse<<<dim3(64, 8), 256, 208384>>>(mainstream, Vb);
    kfine2<<<dim3(2, 128, 8), 256>>>(contexts, (float*)d_out);
}

// round 4
// speedup vs baseline: 1.7700x; 1.2018x over previous
#include <cuda_runtime.h>

// Problem constants
#define BB   8
#define NCTX 3
#define CC   64
#define FF   128
#define HCO  64
#define WCO  64

typedef unsigned long long u64t;

// ------------------------- scratch (device globals) -------------------------
__device__ float g_W2p[64 * 128 * 2];           // packed [opair][f][2]  (qt rows 0-63, k rows 64-127)
__device__ float g_bias2[128];                  // qt bias (Wc^T bf) || bk
__device__ float g_Vwp[128 * 32 * 20];          // padded conv weights [f][cpair][20: 9 f32x2 taps + pad]
__device__ float g_qt[BB * CC * HCO * WCO];     // [b][c][hc][wc]
__device__ float g_vals[BB * CC * HCO * WCO];   // [b][c][hc][wc]
__device__ float g_ml[BB * HCO * WCO];          // main-branch logit

// ------------------------- f32x2 helpers -------------------------
__device__ __forceinline__ u64t splat2(float x) {
    u64t r; asm("mov.b64 %0, {%1, %1};" : "=l"(r) : "f"(x)); return r;
}
__device__ __forceinline__ u64t pack2(float x, float y) {
    u64t r; asm("mov.b64 %0, {%1, %2};" : "=l"(r) : "f"(x), "f"(y)); return r;
}
__device__ __forceinline__ void fma2(u64t& d, u64t a, u64t b) {
    asm("fma.rn.f32x2 %0, %1, %2, %0;" : "+l"(d) : "l"(a), "l"(b));
}
__device__ __forceinline__ float2 unpack2(u64t v) {
    float2 r; asm("mov.b64 {%0, %1}, %2;" : "=f"(r.x), "=f"(r.y) : "l"(v)); return r;
}

// ------------------------- prep kernels -------------------------
__global__ void prep1(const float* __restrict__ Wc, const float* __restrict__ bf,
                      const float* __restrict__ Wf, const float* __restrict__ Wk,
                      const float* __restrict__ bk) {
    int o = blockIdx.x;      // 0..127
    int f = threadIdx.x;     // 0..127
    float v;
    if (o < 64) {
        v = 0.f;
        for (int d = 0; d < 64; d++) v += Wc[d * 64 + o] * Wf[d * 128 + f];
    } else {
        v = Wk[(o - 64) * 128 + f];
    }
    g_W2p[(o >> 1) * 256 + f * 2 + (o & 1)] = v;
    if (f == 0) {
        float bbv;
        if (o < 64) { bbv = 0.f; for (int d = 0; d < 64; d++) bbv += Wc[d * 64 + o] * bf[d]; }
        else bbv = bk[o - 64];
        g_bias2[o] = bbv;
    }
}

// Pack Vw [C][F][3][3] -> g_Vwp [f][cpair][slot<20], slot = tap*2 + p, slots 18,19 = pad
__global__ void prep2(const float* __restrict__ Vw) {
    int i = blockIdx.x * 256 + threadIdx.x;
    if (i >= 128 * 32 * 20) return;
    int slot = i % 20;
    int cp   = (i / 20) % 32;
    int f    = i / (20 * 32);
    float v = 0.f;
    if (slot < 18) {
        int p = slot & 1;
        int tap = slot >> 1;
        v = Vw[((2 * cp + p) * 128 + f) * 9 + tap];
    }
    g_Vwp[i] = v;
}

// ------------------------- coarse kernel -------------------------
// grid (64 hc, 8 b), 256 threads, dyn smem 91648 B -> 2 CTAs/SM.
// smem layout (floats):
//   s_slab = sm + 0     : [3][64][66] = 12672  (phase1 uses [0:4224] as center-row chunk;
//                                               s_qk [128][64]=8192 aliases [0:8192] between phases)
//   s_aux  = sm + 12672 : 10240  (phase1: W2 chunk [64][64][2]=8192 ; conv: Vw subchunk [16][32][20]=10240)
__global__ void __launch_bounds__(256, 2)
kcoarse(const float* __restrict__ ms, const float* __restrict__ Vb) {
    extern __shared__ float sm[];
    float* s_slab = sm;
    float* s_aux  = sm + 12672;

    const int hc  = blockIdx.x;
    const int b   = blockIdx.y;
    const int tid = threadIdx.x;
    const float* mb = ms + (size_t)b * 128 * 4096;

    const int pxg = tid & 15;      // 16 groups of 4 wc
    const int og  = tid >> 4;      // 16 groups of 4 out-pairs
    const int wc0 = pxg * 4;
    const int op0 = og * 4;

    // ---- phase 1: qt & k (1x1), f chunked 2x64, acc in registers ----
    u64t acc[4][4];
    #pragma unroll
    for (int p = 0; p < 4; p++) {
        u64t bi = pack2(g_bias2[(op0 + p) * 2], g_bias2[(op0 + p) * 2 + 1]);
        #pragma unroll
        for (int j = 0; j < 4; j++) acc[p][j] = bi;
    }
    for (int fc = 0; fc < 2; fc++) {
        __syncthreads();
        // center-row activation chunk [64][66] (no halo needed for 1x1)
        for (int i = tid; i < 64 * 64; i += 256) {
            int fl = i >> 6, w = i & 63;
            s_slab[fl * 66 + 1 + w] = mb[(size_t)(fc * 64 + fl) * 4096 + hc * 64 + w];
        }
        // W2 chunk [64 op][64 f][2]
        for (int i = tid; i < 64 * 64; i += 256) {
            int op = i >> 6, fl = i & 63;
            *(float2*)&s_aux[(op * 64 + fl) * 2] = *(const float2*)&g_W2p[(op * 128 + fc * 64 + fl) * 2];
        }
        __syncthreads();
        #pragma unroll 4
        for (int f = 0; f < 64; f++) {
            u64t ms4[4];
            #pragma unroll
            for (int j = 0; j < 4; j++) ms4[j] = splat2(s_slab[f * 66 + 1 + wc0 + j]);
            u64t wp[4];
            #pragma unroll
            for (int p = 0; p < 4; p++) wp[p] = *(const u64t*)&s_aux[((op0 + p) * 64 + f) * 2];
            #pragma unroll
            for (int p = 0; p < 4; p++)
                #pragma unroll
                for (int j = 0; j < 4; j++) fma2(acc[p][j], ms4[j], wp[p]);
        }
    }
    __syncthreads();

    // write qk into smem (aliases slab) + qt to global
    float* s_qk = sm;   // [128][64]
    float* qtb  = g_qt + (size_t)b * 64 * 4096 + hc * 64;
    #pragma unroll
    for (int p = 0; p < 4; p++) {
        int o0 = (op0 + p) * 2;
        #pragma unroll
        for (int j = 0; j < 4; j++) {
            float2 v = unpack2(acc[p][j]);
            s_qk[o0 * 64 + wc0 + j]       = v.x;
            s_qk[(o0 + 1) * 64 + wc0 + j] = v.y;
            if (o0 < 64) {
                qtb[(size_t)o0 * 4096 + wc0 + j]       = v.x;
                qtb[(size_t)(o0 + 1) * 4096 + wc0 + j] = v.y;
            }
        }
    }
    __syncthreads();

    if (tid < 64) {
        float s = 0.f;
        #pragma unroll
        for (int c = 0; c < 64; c++) s += s_qk[c * 64 + tid] * s_qk[(64 + c) * 64 + tid];
        g_ml[((size_t)b * 64 + hc) * 64 + tid] = s;
    }

    // ---- phase 2: conv3x3 (values), f chunked 2x64, subchunked 4x16 for weights ----
    const int cg = tid >> 4;   // 16 groups of 2 ch-pairs (4 channels)
    u64t vac[2][4];
    #pragma unroll
    for (int p = 0; p < 2; p++) {
        u64t bi = pack2(Vb[(cg * 2 + p) * 2], Vb[(cg * 2 + p) * 2 + 1]);
        #pragma unroll
        for (int j = 0; j < 4; j++) vac[p][j] = bi;
    }
    for (int fc = 0; fc < 2; fc++) {
        __syncthreads();   // ml reads / previous chunk compute complete
        // 3-row slab chunk [3][64][66] with zero halo
        for (int i = tid; i < 3 * 64 * 64; i += 256) {
            int w = i & 63;
            int fl = (i >> 6) & 63;
            int r = i >> 12;
            int h = hc - 1 + r;
            float v = (h >= 0 && h < 64) ? mb[(size_t)(fc * 64 + fl) * 4096 + h * 64 + w] : 0.f;
            s_slab[(r * 64 + fl) * 66 + 1 + w] = v;
        }
        for (int i = tid; i < 3 * 64; i += 256) { s_slab[i * 66] = 0.f; s_slab[i * 66 + 65] = 0.f; }
        for (int sub = 0; sub < 4; sub++) {
            __syncthreads();   // prev compute done (and slab/halo visible on sub=0)
            for (int i = tid; i < 2560; i += 256)
                *(float4*)&s_aux[i * 4] = *(const float4*)&g_Vwp[(size_t)(fc * 64 + sub * 16) * 640 + i * 4];
            __syncthreads();
            #pragma unroll 2
            for (int fl = 0; fl < 16; fl++) {
                int f = sub * 16 + fl;
                // activations: 3 rows x 6 cols via float2 LDS, then splat
                u64t mm[3][6];
                #pragma unroll
                for (int r = 0; r < 3; r++) {
                    const float* rp = &s_slab[(r * 64 + f) * 66 + wc0];
                    #pragma unroll
                    for (int kk = 0; kk < 3; kk++) {
                        float2 v = *(const float2*)(rp + 2 * kk);
                        mm[r][2 * kk]     = splat2(v.x);
                        mm[r][2 * kk + 1] = splat2(v.y);
                    }
                }
                // weights: padded 80B rows -> 4x LDS.128 + 1x LDS.64 per pair
                u64t wv[2][9];
                #pragma unroll
                for (int p = 0; p < 2; p++) {
                    const float* wrow = &s_aux[(fl * 32 + cg * 2 + p) * 20];
                    float4 a0 = *(const float4*)(wrow + 0);
                    float4 a1 = *(const float4*)(wrow + 4);
                    float4 a2 = *(const float4*)(wrow + 8);
                    float4 a3 = *(const float4*)(wrow + 12);
                    float2 a4 = *(const float2*)(wrow + 16);
                    wv[p][0] = pack2(a0.x, a0.y); wv[p][1] = pack2(a0.z, a0.w);
                    wv[p][2] = pack2(a1.x, a1.y); wv[p][3] = pack2(a1.z, a1.w);
                    wv[p][4] = pack2(a2.x, a2.y); wv[p][5] = pack2(a2.z, a2.w);
                    wv[p][6] = pack2(a3.x, a3.y); wv[p][7] = pack2(a3.z, a3.w);
                    wv[p][8] = pack2(a4.x, a4.y);
                }
                #pragma unroll
                for (int ky = 0; ky < 3; ky++)
                    #pragma unroll
                    for (int kx = 0; kx < 3; kx++)
                        #pragma unroll
                        for (int p = 0; p < 2; p++)
                            #pragma unroll
                            for (int j = 0; j < 4; j++)
                                fma2(vac[p][j], mm[ky][j + kx], wv[p][ky * 3 + kx]);
            }
        }
    }
    float* vb2 = g_vals + (size_t)b * 64 * 4096 + hc * 64;
    #pragma unroll
    for (int p = 0; p < 2; p++) {
        int c0 = (cg * 2 + p) * 2;
        #pragma unroll
        for (int j = 0; j < 4; j++) {
            float2 v = unpack2(vac[p][j]);
            vb2[(size_t)c0 * 4096 + wc0 + j]       = v.x;
            vb2[(size_t)(c0 + 1) * 4096 + wc0 + j] = v.y;
        }
    }
}

// ------------------------- fine kernel (register-resident, no smem) -------------------------
// grid (4 wq, 128 h, 8 b), 256 threads.
// warp = 4 px x 8 channel-groups (8 ch each); logit reduction via shfl_xor(4),(8),(16).
__global__ void __launch_bounds__(256)
kfine2(const float* __restrict__ ctx, float* __restrict__ out) {
    const int b    = blockIdx.z;
    const int h    = blockIdx.y;
    const int warp = threadIdx.x >> 5;
    const int lane = threadIdx.x & 31;
    const int px   = lane & 3;
    const int cg   = lane >> 2;
    const int w    = blockIdx.x * 32 + warp * 4 + px;
    const int c0   = cg * 8;
    const int hc   = h >> 1;
    const int wc   = w >> 1;

    // context values for my 8 channels x 3 contexts -> registers (read ONCE)
    const float* cb = ctx + ((size_t)(b * 3) * 64 + c0) * 16384 + h * 128 + w;
    float r0[8], r1[8], r2[8];
    #pragma unroll
    for (int i = 0; i < 8; i++) {
        r0[i] = cb[(size_t)i * 16384];
        r1[i] = cb[(size_t)(64 + i) * 16384];
        r2[i] = cb[(size_t)(128 + i) * 16384];
    }

    // partial logits with transformed query
    const float* qb = g_qt + ((size_t)b * 64 + c0) * 4096 + hc * 64 + wc;
    float l0 = 0.f, l1 = 0.f, l2 = 0.f;
    #pragma unroll
    for (int i = 0; i < 8; i++) {
        float q = qb[(size_t)i * 4096];
        l0 += r0[i] * q; l1 += r1[i] * q; l2 += r2[i] * q;
    }
    // reduce across the 8 channel groups (lane bits 2,3,4)
    l0 += __shfl_xor_sync(0xFFFFFFFFu, l0, 4);
    l0 += __shfl_xor_sync(0xFFFFFFFFu, l0, 8);
    l0 += __shfl_xor_sync(0xFFFFFFFFu, l0, 16);
    l1 += __shfl_xor_sync(0xFFFFFFFFu, l1, 4);
    l1 += __shfl_xor_sync(0xFFFFFFFFu, l1, 8);
    l1 += __shfl_xor_sync(0xFFFFFFFFu, l1, 16);
    l2 += __shfl_xor_sync(0xFFFFFFFFu, l2, 4);
    l2 += __shfl_xor_sync(0xFFFFFFFFu, l2, 8);
    l2 += __shfl_xor_sync(0xFFFFFFFFu, l2, 16);

    float l3 = g_ml[((size_t)b * 64 + hc) * 64 + wc];

    float mx = fmaxf(fmaxf(l0, l1), fmaxf(l2, l3));
    float e0 = __expf(l0 - mx), e1 = __expf(l1 - mx);
    float e2 = __expf(l2 - mx), e3 = __expf(l3 - mx);
    float inv = 1.f / (e0 + e1 + e2 + e3);
    float a0 = e0 * inv, a1 = e1 * inv, a2 = e2 * inv, a3 = e3 * inv;

    const float* vb = g_vals + ((size_t)b * 64 + c0) * 4096 + hc * 64 + wc;
    float* ob = out + ((size_t)b * 64 + c0) * 16384 + h * 128 + w;
    #pragma unroll
    for (int i = 0; i < 8; i++) {
        float o = r0[i] * a0 + r1[i] * a1 + r2[i] * a2 + vb[(size_t)i * 4096] * a3;
        ob[(size_t)i * 16384] = o;
    }
}

// ------------------------- launch -------------------------
extern "C" void kernel_launch(void* const* d_in, const int* in_sizes, int n_in,
                              void* d_out, int out_size) {
    const float* contexts   = (const float*)d_in[0];
    const float* mainstream = (const float*)d_in[1];
    const float* Wc = (const float*)d_in[2];
    // d_in[3] = bc: adds a constant to every logit -> softmax-invariant -> unused
    const float* Wf = (const float*)d_in[4];
    const float* bf = (const float*)d_in[5];
    const float* Wk = (const float*)d_in[6];
    const float* bk = (const float*)d_in[7];
    const float* Vw = (const float*)d_in[8];
    const float* Vb = (const float*)d_in[9];

    cudaFuncSetAttribute(kcoarse, cudaFuncAttributeMaxDynamicSharedMemorySize, 91648);

    prep1<<<128, 128>>>(Wc, bf, Wf, Wk, bk);
    prep2<<<320, 256>>>(Vw);
    kcoarse<<<dim3(64, 8), 256, 91648>>>(mainstream, Vb);
    kfine2<<<dim3(4, 128, 8), 256>>>(contexts, (float*)d_out);
}